// round 14
// baseline (speedup 1.0000x reference)
#include <cuda_runtime.h>
#include <cuda_bf16.h>
#include <cstdint>

#define NHEAD 16
#define DKV   64
#define NSEQ  2048
#define DMOD  1024
#define LOG2E 1.4426950408889634f

__device__ float g_G[NHEAD][DKV][DKV];
__device__ float g_vk[NHEAD][DKV];
__device__ __align__(16) __nv_bfloat16 g_Qh[NSEQ][DKV];
__device__ __align__(16) __nv_bfloat16 g_Ql[NSEQ][DKV];
// Packed fragment-order K: per row m, 256B = [ks][tg] 16B blocks
//  {hi(k,k+1), hi(k+8,k+9), lo(k,k+1), lo(k+8,k+9)},  k = ks*16 + tg*2
__device__ __align__(16) unsigned char g_Kp[NHEAD][NSEQ][256];
__device__ __align__(16) float g_betac[NHEAD][NSEQ];
__device__ float g_S[NHEAD][NSEQ];    // softmax row sums (accumulated)
__device__ float g_w[NHEAD][NSEQ];
__device__ float g_u[NHEAD][DKV];
__device__ float g_pooled[DMOD];

// ---------------- helpers ----------------
__device__ __forceinline__ void cpa16(void* smem_dst, const void* gsrc) {
    unsigned s = (unsigned)__cvta_generic_to_shared(smem_dst);
    asm volatile("cp.async.cg.shared.global [%0], [%1], 16;" :: "r"(s), "l"(gsrc));
}
#define CPCOMMIT() asm volatile("cp.async.commit_group;" ::: "memory")
#define CPWAIT(n)  asm volatile("cp.async.wait_group %0;" :: "n"(n) : "memory")

__device__ __forceinline__ float ex2(float x) {
    float y; asm("ex2.approx.f32 %0, %1;" : "=f"(y) : "f"(x)); return y;
}
__device__ __forceinline__ void mma16816(float* d, const uint32_t* a,
                                         uint32_t b0, uint32_t b1) {
    asm volatile(
        "mma.sync.aligned.m16n8k16.row.col.f32.bf16.bf16.f32 "
        "{%0,%1,%2,%3}, {%4,%5,%6,%7}, {%8,%9}, {%0,%1,%2,%3};"
        : "+f"(d[0]), "+f"(d[1]), "+f"(d[2]), "+f"(d[3])
        : "r"(a[0]), "r"(a[1]), "r"(a[2]), "r"(a[3]), "r"(b0), "r"(b1));
}
__device__ __forceinline__ uint32_t packbf2(float a, float b) {
    __nv_bfloat162 v = __floats2bfloat162_rn(a, b);
    return *(uint32_t*)&v;
}

// ---------------- K0 ----------------
__global__ void kz() {
    int i = blockIdx.x * blockDim.x + threadIdx.x;
    if (i < NHEAD * DKV * DKV) ((float*)g_G)[i]  = 0.f;
    if (i < NHEAD * DKV)       ((float*)g_vk)[i] = 0.f;
    if (i < NHEAD * NSEQ)      ((float*)g_w)[i]  = 0.f;
    if (i < NHEAD * NSEQ)      ((float*)g_S)[i]  = 0.f;
    if (i < NHEAD * DKV)       ((float*)g_u)[i]  = 0.f;
    if (i < DMOD)              g_pooled[i]       = 0.f;
}

// ---------------- K1: G_h = Wq_h Wk_h^T / 8, vk_h = Wk_h bq_h / 8 ----------------
__global__ void k1(const float* __restrict__ Wq, const float* __restrict__ Wk,
                   const float* __restrict__ bq) {
    __shared__ float wq_s[64][65];
    __shared__ float wk_s[64][65];
    int h = blockIdx.x, d0 = blockIdx.y * 64, t = threadIdx.x;
    #pragma unroll
    for (int j = 0; j < 16; j++) {
        int idx = t + 256 * j, row = idx >> 6, col = idx & 63;
        wq_s[row][col] = Wq[(h * 64 + row) * DMOD + d0 + col];
        wk_s[row][col] = Wk[(h * 64 + row) * DMOD + d0 + col];
    }
    __syncthreads();
    int a0 = (t >> 4) << 2, b0 = (t & 15) << 2;
    float acc[4][4] = {};
    for (int dd = 0; dd < 64; dd++) {
        float qa[4], kb[4];
        #pragma unroll
        for (int i = 0; i < 4; i++) qa[i] = wq_s[a0 + i][dd];
        #pragma unroll
        for (int j = 0; j < 4; j++) kb[j] = wk_s[b0 + j][dd];
        #pragma unroll
        for (int i = 0; i < 4; i++)
            #pragma unroll
            for (int j = 0; j < 4; j++) acc[i][j] += qa[i] * kb[j];
    }
    #pragma unroll
    for (int i = 0; i < 4; i++)
        #pragma unroll
        for (int j = 0; j < 4; j++)
            atomicAdd(&g_G[h][a0 + i][b0 + j], acc[i][j] * 0.125f);
    if (t < 64) {
        float s = 0.f;
        for (int dd = 0; dd < 64; dd++) s += wk_s[t][dd] * bq[h * DMOD + d0 + dd];
        atomicAdd(&g_vk[h][t], s * 0.125f);
    }
}

// ---------------- KQ: bf16 hi/lo split of log2e * queries ----------------
__global__ void kq(const float* __restrict__ queries) {
    int i = blockIdx.x * 256 + threadIdx.x;
    float x = queries[i] * LOG2E;
    __nv_bfloat16 hi = __float2bfloat16(x);
    ((__nv_bfloat16*)g_Qh)[i] = hi;
    ((__nv_bfloat16*)g_Ql)[i] = __float2bfloat16(x - __bfloat162float(hi));
}

// ---------------- K2: Kp = pack(keys @ G^T) fragment-order, beta_c ----------------
// 128-row m-tiles (G amortized 2x), grid (16, 16), 256 threads.
__global__ void k2(const float* __restrict__ keys) {
    __shared__ __align__(16) float G_s[64][64];
    __shared__ __align__(16) float k_s[128][68];
    __shared__ float vk_s[64];
    int h = blockIdx.y, m0 = blockIdx.x * 128, t = threadIdx.x;
    #pragma unroll
    for (int j = 0; j < 16; j++) {
        int idx = t + 256 * j;
        ((float*)G_s)[idx] = ((const float*)g_G)[h * 4096 + idx];
    }
    #pragma unroll
    for (int j = 0; j < 32; j++) {
        int idx = t + 256 * j;           // 0..8191
        int r = idx >> 6, col = idx & 63;
        k_s[r][col] = keys[(m0 + r) * DKV + col];
    }
    if (t < 64) vk_s[t] = g_vk[h][t];
    __syncthreads();
    int ml = t & 127, kb2 = t >> 7;      // kb2 in {0,1}: k-range [kb2*32, kb2*32+32)
    int k0 = kb2 << 5;
    float acc[32] = {};
    #pragma unroll
    for (int bc = 0; bc < 4; bc++) {
        float kv[16];
        #pragma unroll
        for (int j = 0; j < 4; j++) {
            float4 v = *(const float4*)&k_s[ml][bc * 16 + j * 4];
            kv[4*j] = v.x; kv[4*j+1] = v.y; kv[4*j+2] = v.z; kv[4*j+3] = v.w;
        }
        #pragma unroll
        for (int kk = 0; kk < 32; kk++) {
            #pragma unroll
            for (int j = 0; j < 4; j++) {
                float4 g = *(const float4*)&G_s[k0 + kk][bc * 16 + j * 4];
                acc[kk] += g.x * kv[4*j] + g.y * kv[4*j+1] + g.z * kv[4*j+2] + g.w * kv[4*j+3];
            }
        }
    }
    float hi[32], lo[32];
    #pragma unroll
    for (int kk = 0; kk < 32; kk++) {
        __nv_bfloat16 hb = __float2bfloat16(acc[kk]);
        hi[kk] = __bfloat162float(hb);
        lo[kk] = acc[kk] - hi[kk];
    }
    // pack: two 16-k blocks (kb2*2, kb2*2+1), each 64B of 4 tg-groups
    #pragma unroll
    for (int blk = 0; blk < 2; blk++) {
        unsigned char* dst = &g_Kp[h][m0 + ml][(kb2 * 2 + blk) * 64];
        int kb = blk * 16;
        #pragma unroll
        for (int tg = 0; tg < 4; tg++) {
            uint4 v;
            v.x = packbf2(hi[kb + 2*tg],     hi[kb + 2*tg + 1]);
            v.y = packbf2(hi[kb + 2*tg + 8], hi[kb + 2*tg + 9]);
            v.z = packbf2(lo[kb + 2*tg],     lo[kb + 2*tg + 1]);
            v.w = packbf2(lo[kb + 2*tg + 8], lo[kb + 2*tg + 9]);
            *(uint4*)(dst + tg * 16) = v;
        }
    }
    if (t < 128) {
        float s = 0.f;
        for (int k = 0; k < 64; k++) s += k_s[t][k] * vk_s[k];
        g_betac[h][m0 + t] = s * LOG2E;
    }
}

// ---------------- K3a/K3b shared machinery ----------------
#define SM_BETA 0
#define SM_W    8192
#define SM_BUF  16384
#define BUFSZ   32768
#define SM_TOT  (SM_BUF + 2 * BUFSZ)   // 81920

__device__ __forceinline__ void load_chunk(char* smem, const char* kp, int c, int t) {
    char* dst = smem + SM_BUF + (c & 1) * BUFSZ;
    const char* src = kp + c * 32768;
    #pragma unroll
    for (int i = 0; i < 16; i++)
        cpa16(dst + (t + 128 * i) * 16, src + (t + 128 * i) * 16);
}

// Load warp's 32 Q rows (2 tiles, hi/lo), 4 k-steps into fragments
__device__ __forceinline__ void load_qfrag(uint32_t qah[2][4][4], uint32_t qal[2][4][4],
                                           int nw, int g, int tg) {
    const uint32_t* qh32 = (const uint32_t*)&g_Qh[0][0];
    const uint32_t* ql32 = (const uint32_t*)&g_Ql[0][0];
    #pragma unroll
    for (int T = 0; T < 2; T++) {
        int r0 = (nw + T * 16 + g) * 32, r1 = r0 + 8 * 32;
        #pragma unroll
        for (int ks = 0; ks < 4; ks++) {
            int o = ks * 8 + tg;
            qah[T][ks][0] = qh32[r0 + o];     qah[T][ks][1] = qh32[r1 + o];
            qah[T][ks][2] = qh32[r0 + o + 4]; qah[T][ks][3] = qh32[r1 + o + 4];
            qal[T][ks][0] = ql32[r0 + o];     qal[T][ks][1] = ql32[r1 + o];
            qal[T][ks][2] = ql32[r0 + o + 4]; qal[T][ks][3] = ql32[r1 + o + 4];
        }
    }
}

// Compute one 16-m-tile of 6 MMA products -> 16 exp values (4 n-cols x 4 row-frags)
#define CHUNK_MMA_BODY(p0, qah, qal, dA0, dA1, dB0, dB1)                        \
    _Pragma("unroll")                                                           \
    for (int ks = 0; ks < 4; ks++) {                                            \
        uint4 v0 = *(const uint4*)((p0) + ks * 64);                             \
        uint4 v1 = *(const uint4*)((p0) + 8 * 256 + ks * 64);                   \
        _Pragma("unroll")                                                       \
        for (int T = 0; T < 2; T++) {                                           \
            mma16816(dA0[T], qah[T][ks], v0.x, v0.y);                           \
            mma16816(dA1[T], qah[T][ks], v1.x, v1.y);                           \
            mma16816(dB0[T], qal[T][ks], v0.x, v0.y);                           \
            mma16816(dB1[T], qal[T][ks], v1.x, v1.y);                           \
            mma16816(dB0[T], qah[T][ks], v0.z, v0.w);                           \
            mma16816(dB1[T], qah[T][ks], v1.z, v1.w);                           \
        }                                                                       \
    }

// ---------------- K3a: pass 0 — partial row sums ----------------
// grid (16 n-blocks, 16 heads, 2 m-halves), 128 threads, 2 blocks/SM.
__global__ void __launch_bounds__(128, 2) k3a() {
    extern __shared__ char smem[];
    int t = threadIdx.x, w = t >> 5, l = t & 31;
    int g = l >> 2, tg = l & 3;
    int h = blockIdx.y, n0 = blockIdx.x * 128, mh = blockIdx.z;
    int nw = n0 + w * 32, c0 = mh * 8;

    {
        const float* bp = &g_betac[h][0];
        float* bs = (float*)(smem + SM_BETA);
        #pragma unroll
        for (int i = 0; i < 16; i++) bs[t + 128 * i] = bp[t + 128 * i];
    }
    uint32_t qah[2][4][4], qal[2][4][4];
    load_qfrag(qah, qal, nw, g, tg);

    const char* kp = (const char*)&g_Kp[h][0][0];
    const float* beta_s = (const float*)(smem + SM_BETA);

    load_chunk(smem, kp, c0, t); CPCOMMIT();
    load_chunk(smem, kp, c0 + 1, t); CPCOMMIT();

    float S[4] = {0.f, 0.f, 0.f, 0.f};

    for (int cc = 0; cc < 8; cc++) {
        int c = c0 + cc;
        if (cc < 7) { CPWAIT(1); } else { CPWAIT(0); }
        __syncthreads();
        const char* bufb = smem + SM_BUF + (c & 1) * BUFSZ;
        const char* lanebase = bufb + g * 256 + tg * 16;
        #pragma unroll
        for (int mp = 0; mp < 8; mp++) {
            float dA0[2][4] = {}, dA1[2][4] = {};
            float dB0[2][4] = {}, dB1[2][4] = {};
            const char* p0 = lanebase + mp * (16 * 256);
            CHUNK_MMA_BODY(p0, qah, qal, dA0, dA1, dB0, dB1)
            int mb0 = c * 128 + mp * 16;
            float2 be0 = *(const float2*)(beta_s + mb0 + 2 * tg);
            float2 be1 = *(const float2*)(beta_s + mb0 + 8 + 2 * tg);
            #pragma unroll
            for (int T = 0; T < 2; T++) {
                float e0 = ex2(dA0[T][0] + dB0[T][0] + be0.x);
                float e1 = ex2(dA0[T][1] + dB0[T][1] + be0.y);
                float e2 = ex2(dA0[T][2] + dB0[T][2] + be0.x);
                float e3 = ex2(dA0[T][3] + dB0[T][3] + be0.y);
                float f0 = ex2(dA1[T][0] + dB1[T][0] + be1.x);
                float f1 = ex2(dA1[T][1] + dB1[T][1] + be1.y);
                float f2 = ex2(dA1[T][2] + dB1[T][2] + be1.x);
                float f3 = ex2(dA1[T][3] + dB1[T][3] + be1.y);
                S[2 * T]     += (e0 + e1) + (f0 + f1);
                S[2 * T + 1] += (e2 + e3) + (f2 + f3);
            }
        }
        if (cc + 2 < 8) {
            __syncthreads();
            load_chunk(smem, kp, c + 2, t); CPCOMMIT();
        }
    }
    #pragma unroll
    for (int i = 0; i < 4; i++) {
        S[i] += __shfl_xor_sync(0xffffffffu, S[i], 1);
        S[i] += __shfl_xor_sync(0xffffffffu, S[i], 2);
    }
    if (tg == 0) {
        #pragma unroll
        for (int i = 0; i < 4; i++) {
            int row = nw + (i >> 1) * 16 + g + (i & 1) * 8;
            atomicAdd(&g_S[h][row], S[i]);
        }
    }
}

// ---------------- K3b: pass 1 — normalized column sums ----------------
__global__ void __launch_bounds__(128, 2) k3b() {
    extern __shared__ char smem[];
    int t = threadIdx.x, w = t >> 5, l = t & 31;
    int g = l >> 2, tg = l & 3;
    int h = blockIdx.y, n0 = blockIdx.x * 128, mh = blockIdx.z;
    int nw = n0 + w * 32, c0 = mh * 8;

    {
        const float* bp = &g_betac[h][0];
        float* bs = (float*)(smem + SM_BETA);
        float* ws = (float*)(smem + SM_W);
        #pragma unroll
        for (int i = 0; i < 16; i++) {
            bs[t + 128 * i] = bp[t + 128 * i];
            ws[t + 128 * i] = 0.f;
        }
    }
    uint32_t qah[2][4][4], qal[2][4][4];
    load_qfrag(qah, qal, nw, g, tg);

    float inv[4];
    #pragma unroll
    for (int i = 0; i < 4; i++) {
        int row = nw + (i >> 1) * 16 + g + (i & 1) * 8;
        inv[i] = 1.f / g_S[h][row];
    }

    const char* kp = (const char*)&g_Kp[h][0][0];
    const float* beta_s = (const float*)(smem + SM_BETA);
    float* w_s = (float*)(smem + SM_W);

    load_chunk(smem, kp, c0, t); CPCOMMIT();
    load_chunk(smem, kp, c0 + 1, t); CPCOMMIT();

    for (int cc = 0; cc < 8; cc++) {
        int c = c0 + cc;
        if (cc < 7) { CPWAIT(1); } else { CPWAIT(0); }
        __syncthreads();
        const char* bufb = smem + SM_BUF + (c & 1) * BUFSZ;
        const char* lanebase = bufb + g * 256 + tg * 16;
        #pragma unroll
        for (int mp = 0; mp < 8; mp++) {
            float dA0[2][4] = {}, dA1[2][4] = {};
            float dB0[2][4] = {}, dB1[2][4] = {};
            const char* p0 = lanebase + mp * (16 * 256);
            CHUNK_MMA_BODY(p0, qah, qal, dA0, dA1, dB0, dB1)
            int mb0 = c * 128 + mp * 16;
            float2 be0 = *(const float2*)(beta_s + mb0 + 2 * tg);
            float2 be1 = *(const float2*)(beta_s + mb0 + 8 + 2 * tg);
            float v00 = 0.f, v01 = 0.f, v10 = 0.f, v11 = 0.f;
            #pragma unroll
            for (int T = 0; T < 2; T++) {
                float e0 = ex2(dA0[T][0] + dB0[T][0] + be0.x);
                float e1 = ex2(dA0[T][1] + dB0[T][1] + be0.y);
                float e2 = ex2(dA0[T][2] + dB0[T][2] + be0.x);
                float e3 = ex2(dA0[T][3] + dB0[T][3] + be0.y);
                float f0 = ex2(dA1[T][0] + dB1[T][0] + be1.x);
                float f1 = ex2(dA1[T][1] + dB1[T][1] + be1.y);
                float f2 = ex2(dA1[T][2] + dB1[T][2] + be1.x);
                float f3 = ex2(dA1[T][3] + dB1[T][3] + be1.y);
                v00 += e0 * inv[2 * T] + e2 * inv[2 * T + 1];
                v01 += e1 * inv[2 * T] + e3 * inv[2 * T + 1];
                v10 += f0 * inv[2 * T] + f2 * inv[2 * T + 1];
                v11 += f1 * inv[2 * T] + f3 * inv[2 * T + 1];
            }
            #pragma unroll
            for (int off = 4; off < 32; off <<= 1) {
                v00 += __shfl_xor_sync(0xffffffffu, v00, off);
                v01 += __shfl_xor_sync(0xffffffffu, v01, off);
                v10 += __shfl_xor_sync(0xffffffffu, v10, off);
                v11 += __shfl_xor_sync(0xffffffffu, v11, off);
            }
            if (l < 4) {
                atomicAdd(&w_s[mb0 + 2 * tg], v00);
                atomicAdd(&w_s[mb0 + 2 * tg + 1], v01);
                atomicAdd(&w_s[mb0 + 8 + 2 * tg], v10);
                atomicAdd(&w_s[mb0 + 8 + 2 * tg + 1], v11);
            }
        }
        if (cc + 2 < 8) {
            __syncthreads();
            load_chunk(smem, kp, c + 2, t); CPCOMMIT();
        }
    }
    __syncthreads();
    #pragma unroll
    for (int i = 0; i < 8; i++) {
        int m = c0 * 128 + t + 128 * i;
        atomicAdd(&g_w[h][m], w_s[m]);
    }
}

// ---------------- K4a: u[h] += w[h] strip @ values strip ----------------
__global__ void k4a(const float* __restrict__ values) {
    __shared__ float w_s[512];
    __shared__ float part[4][64];
    int h = blockIdx.x, strip = blockIdx.y, t = threadIdx.x;
    int mbase = strip * 512;
    w_s[t]       = g_w[h][mbase + t];
    w_s[t + 256] = g_w[h][mbase + 256 + t];
    __syncthreads();
    int v = t & 63, s = t >> 6;
    float acc = 0.f;
    for (int m = s * 128; m < s * 128 + 128; m++)
        acc += w_s[m] * values[(mbase + m) * DKV + v];
    part[s][v] = acc;
    __syncthreads();
    if (t < 64)
        atomicAdd(&g_u[h][t], part[0][t] + part[1][t] + part[2][t] + part[3][t]);
}

// ---------------- K4b: pooled[d] += u strip . Wv strip (+ bias on strip 0) ----------------
__global__ void k4b(const float* __restrict__ Wv, const float* __restrict__ bv) {
    __shared__ float u_s[256];
    int t = threadIdx.x, d = blockIdx.x * 256 + t, strip = blockIdx.y;
    u_s[t] = ((const float*)g_u)[strip * 256 + t];
    __syncthreads();
    float acc = 0.f;
    #pragma unroll 4
    for (int hv = 0; hv < 256; hv++) acc += u_s[hv] * Wv[(strip * 256 + hv) * DMOD + d];
    if (strip == 0) {
        float bsum = 0.f;
        #pragma unroll
        for (int h2 = 0; h2 < NHEAD; h2++) bsum += bv[h2 * DMOD + d];
        acc += 2048.f * bsum;
    }
    atomicAdd(&g_pooled[d], acc);
}

// ---------------- K4c: out[d] = pooled . Wo[d,:] + bo[d] ----------------
__global__ void k4c(const float* __restrict__ Wo, const float* __restrict__ bo,
                    float* __restrict__ out) {
    __shared__ __align__(16) float p_s[1024];
    int t = threadIdx.x;
    #pragma unroll
    for (int j = 0; j < 4; j++) p_s[t + 256 * j] = g_pooled[t + 256 * j];
    __syncthreads();
    int w = t >> 5, l = t & 31, d = blockIdx.x * 8 + w;
    float acc = 0.f;
    #pragma unroll
    for (int i = 0; i < 8; i++) {
        int e = i * 128 + l * 4;
        float4 wo = *(const float4*)&Wo[d * 1024 + e];
        float4 p  = *(const float4*)&p_s[e];
        acc += wo.x * p.x + wo.y * p.y + wo.z * p.z + wo.w * p.w;
    }
    #pragma unroll
    for (int off = 16; off; off >>= 1) acc += __shfl_xor_sync(0xffffffffu, acc, off);
    if (l == 0) out[d] = acc + bo[d];
}

// ---------------- launch ----------------
extern "C" void kernel_launch(void* const* d_in, const int* in_sizes, int n_in,
                              void* d_out, int out_size) {
    const float* queries = (const float*)d_in[0];
    const float* keys    = (const float*)d_in[1];
    const float* values  = (const float*)d_in[2];
    const float* Wq      = (const float*)d_in[3];
    const float* bq      = (const float*)d_in[4];
    const float* Wk      = (const float*)d_in[5];
    (void)d_in[6];  // bk: row-constant in softmax -> drops
    const float* Wv      = (const float*)d_in[7];
    const float* bv      = (const float*)d_in[8];
    const float* Wo      = (const float*)d_in[9];
    const float* bo      = (const float*)d_in[10];
    float* out = (float*)d_out;

    cudaFuncSetAttribute(k3a, cudaFuncAttributeMaxDynamicSharedMemorySize, SM_TOT);
    cudaFuncSetAttribute(k3b, cudaFuncAttributeMaxDynamicSharedMemorySize, SM_TOT);

    kz <<<256, 256>>>();
    kq <<<512, 256>>>(queries);
    k1 <<<dim3(16, 16), 256>>>(Wq, Wk, bq);
    k2 <<<dim3(16, 16), 256>>>(keys);
    k3a<<<dim3(16, 16, 2), 128, SM_TOT>>>();
    k3b<<<dim3(16, 16, 2), 128, SM_TOT>>>();
    k4a<<<dim3(16, 4), 256>>>(values);
    k4b<<<dim3(4, 4), 256>>>(Wv, bv);
    k4c<<<128, 256>>>(Wo, bo, out);
}

// round 15
// speedup vs baseline: 1.6739x; 1.6739x over previous
#include <cuda_runtime.h>
#include <cuda_bf16.h>
#include <cstdint>

#define NHEAD 16
#define DKV   64
#define NSEQ  2048
#define DMOD  1024
#define LOG2E 1.4426950408889634f

__device__ float g_G[NHEAD][DKV][DKV];
__device__ float g_vk[NHEAD][DKV];
__device__ __align__(16) __nv_bfloat16 g_Qh[NSEQ][DKV];
__device__ __align__(16) __nv_bfloat16 g_Ql[NSEQ][DKV];
// Packed fragment-order K: per row m, 256B = [ks][tg] 16B blocks
//  {hi(k,k+1), hi(k+8,k+9), lo(k,k+1), lo(k+8,k+9)},  k = ks*16 + tg*2
__device__ __align__(16) unsigned char g_Kp[NHEAD][NSEQ][256];
__device__ __align__(16) float g_betac[NHEAD][NSEQ];
__device__ float g_w[NHEAD][NSEQ];
__device__ float g_u[NHEAD][DKV];
__device__ float g_pooled[DMOD];

// ---------------- helpers ----------------
__device__ __forceinline__ void cpa16(void* smem_dst, const void* gsrc) {
    unsigned s = (unsigned)__cvta_generic_to_shared(smem_dst);
    asm volatile("cp.async.cg.shared.global [%0], [%1], 16;" :: "r"(s), "l"(gsrc));
}
#define CPCOMMIT() asm volatile("cp.async.commit_group;" ::: "memory")
#define CPWAIT(n)  asm volatile("cp.async.wait_group %0;" :: "n"(n) : "memory")

__device__ __forceinline__ float ex2(float x) {
    float y; asm("ex2.approx.f32 %0, %1;" : "=f"(y) : "f"(x)); return y;
}
__device__ __forceinline__ void mma16816(float* d, const uint32_t* a,
                                         uint32_t b0, uint32_t b1) {
    asm volatile(
        "mma.sync.aligned.m16n8k16.row.col.f32.bf16.bf16.f32 "
        "{%0,%1,%2,%3}, {%4,%5,%6,%7}, {%8,%9}, {%0,%1,%2,%3};"
        : "+f"(d[0]), "+f"(d[1]), "+f"(d[2]), "+f"(d[3])
        : "r"(a[0]), "r"(a[1]), "r"(a[2]), "r"(a[3]), "r"(b0), "r"(b1));
}
__device__ __forceinline__ uint32_t packbf2(float a, float b) {
    __nv_bfloat162 v = __floats2bfloat162_rn(a, b);
    return *(uint32_t*)&v;
}

// ---------------- KQ: zero scratch + bf16 hi/lo split of log2e * queries ----------------
__global__ void kq(const float* __restrict__ queries) {
    int i = blockIdx.x * 256 + threadIdx.x;    // 131072 threads
    // zeroing (first 65536 cover all)
    if (i < NHEAD * DKV * DKV) ((float*)g_G)[i]  = 0.f;
    if (i < NHEAD * DKV)       ((float*)g_vk)[i] = 0.f;
    if (i < NHEAD * NSEQ)      ((float*)g_w)[i]  = 0.f;
    if (i < NHEAD * DKV)       ((float*)g_u)[i]  = 0.f;
    if (i < DMOD)              g_pooled[i]       = 0.f;
    float x = queries[i] * LOG2E;
    __nv_bfloat16 hi = __float2bfloat16(x);
    ((__nv_bfloat16*)g_Qh)[i] = hi;
    ((__nv_bfloat16*)g_Ql)[i] = __float2bfloat16(x - __bfloat162float(hi));
}

// ---------------- K1: G_h = Wq_h Wk_h^T / 8, vk_h = Wk_h bq_h / 8 ----------------
__global__ void k1(const float* __restrict__ Wq, const float* __restrict__ Wk,
                   const float* __restrict__ bq) {
    __shared__ float wq_s[64][65];
    __shared__ float wk_s[64][65];
    int h = blockIdx.x, d0 = blockIdx.y * 64, t = threadIdx.x;
    #pragma unroll
    for (int j = 0; j < 16; j++) {
        int idx = t + 256 * j, row = idx >> 6, col = idx & 63;
        wq_s[row][col] = Wq[(h * 64 + row) * DMOD + d0 + col];
        wk_s[row][col] = Wk[(h * 64 + row) * DMOD + d0 + col];
    }
    __syncthreads();
    int a0 = (t >> 4) << 2, b0 = (t & 15) << 2;
    float acc[4][4] = {};
    for (int dd = 0; dd < 64; dd++) {
        float qa[4], kb[4];
        #pragma unroll
        for (int i = 0; i < 4; i++) qa[i] = wq_s[a0 + i][dd];
        #pragma unroll
        for (int j = 0; j < 4; j++) kb[j] = wk_s[b0 + j][dd];
        #pragma unroll
        for (int i = 0; i < 4; i++)
            #pragma unroll
            for (int j = 0; j < 4; j++) acc[i][j] += qa[i] * kb[j];
    }
    #pragma unroll
    for (int i = 0; i < 4; i++)
        #pragma unroll
        for (int j = 0; j < 4; j++)
            atomicAdd(&g_G[h][a0 + i][b0 + j], acc[i][j] * 0.125f);
    if (t < 64) {
        float s = 0.f;
        for (int dd = 0; dd < 64; dd++) s += wk_s[t][dd] * bq[h * DMOD + d0 + dd];
        atomicAdd(&g_vk[h][t], s * 0.125f);
    }
}

// ---------------- K2: Kp = pack(keys @ G^T) fragment-order, beta_c ----------------
// 64-row m-tiles (R13 version), grid (32, 16), 256 threads.
__global__ void k2(const float* __restrict__ keys) {
    __shared__ __align__(16) float G_s[64][64];
    __shared__ __align__(16) float k_s[64][68];
    __shared__ float vk_s[64];
    int h = blockIdx.y, m0 = blockIdx.x * 64, t = threadIdx.x;
    #pragma unroll
    for (int j = 0; j < 16; j++) {
        int idx = t + 256 * j;
        ((float*)G_s)[idx] = ((const float*)g_G)[h * 4096 + idx];
        int r = idx >> 6, col = idx & 63;
        k_s[r][col] = keys[(m0 + r) * DKV + col];
    }
    if (t < 64) vk_s[t] = g_vk[h][t];
    __syncthreads();
    int ml = t & 63, ksb = t >> 6;
    int k0 = ksb << 4;
    float acc[16] = {};
    #pragma unroll
    for (int bc = 0; bc < 4; bc++) {
        float kv[16];
        #pragma unroll
        for (int j = 0; j < 4; j++) {
            float4 v = *(const float4*)&k_s[ml][bc * 16 + j * 4];
            kv[4*j] = v.x; kv[4*j+1] = v.y; kv[4*j+2] = v.z; kv[4*j+3] = v.w;
        }
        #pragma unroll
        for (int kk = 0; kk < 16; kk++) {
            #pragma unroll
            for (int j = 0; j < 4; j++) {
                float4 g = *(const float4*)&G_s[k0 + kk][bc * 16 + j * 4];
                acc[kk] += g.x * kv[4*j] + g.y * kv[4*j+1] + g.z * kv[4*j+2] + g.w * kv[4*j+3];
            }
        }
    }
    float hi[16], lo[16];
    #pragma unroll
    for (int kk = 0; kk < 16; kk++) {
        __nv_bfloat16 hb = __float2bfloat16(acc[kk]);
        hi[kk] = __bfloat162float(hb);
        lo[kk] = acc[kk] - hi[kk];
    }
    unsigned char* dst = &g_Kp[h][m0 + ml][ksb * 64];
    #pragma unroll
    for (int tg = 0; tg < 4; tg++) {
        uint4 v;
        v.x = packbf2(hi[2*tg],     hi[2*tg + 1]);
        v.y = packbf2(hi[2*tg + 8], hi[2*tg + 9]);
        v.z = packbf2(lo[2*tg],     lo[2*tg + 1]);
        v.w = packbf2(lo[2*tg + 8], lo[2*tg + 9]);
        *(uint4*)(dst + tg * 16) = v;
    }
    if (t < 64) {
        float s = 0.f;
        for (int k = 0; k < 64; k++) s += k_s[t][k] * vk_s[k];
        g_betac[h][m0 + t] = s * LOG2E;
    }
}

// ---------------- K3: HMMA logits + softmax + column-sum (two-pass, packed B) ----------------
// grid (16 row-blocks of 128, 16 heads), 128 threads = 4 warps, 2 blocks/SM.
// Single fused accumulator per (T, n-tile): all 3 hi/lo products chain into
// the same MMA accumulator (saves 128 FADD per warp-chunk vs split chains).
#define SM_BETA 0
#define SM_W    8192
#define SM_BUF  16384
#define BUFSZ   32768
#define SM_TOT  (SM_BUF + 2 * BUFSZ)   // 81920

__device__ __forceinline__ void load_chunk(char* smem, const char* kp, int c, int t) {
    char* dst = smem + SM_BUF + (c & 1) * BUFSZ;
    const char* src = kp + c * 32768;
    #pragma unroll
    for (int i = 0; i < 16; i++)
        cpa16(dst + (t + 128 * i) * 16, src + (t + 128 * i) * 16);
}

__global__ void __launch_bounds__(128, 2) k3() {
    extern __shared__ char smem[];
    int t = threadIdx.x, w = t >> 5, l = t & 31;
    int g = l >> 2, tg = l & 3;
    int h = blockIdx.y, n0 = blockIdx.x * 128;
    int nw = n0 + w * 32;

    // beta + w_s init
    {
        const float* bp = &g_betac[h][0];
        float* bs = (float*)(smem + SM_BETA);
        float* ws = (float*)(smem + SM_W);
        #pragma unroll
        for (int i = 0; i < 16; i++) {
            bs[t + 128 * i] = bp[t + 128 * i];
            ws[t + 128 * i] = 0.f;
        }
    }

    // A fragments: warp's 32 Q rows (2 tiles, hi/lo), 4 k-steps — resident all kernel
    uint32_t qah[2][4][4], qal[2][4][4];
    {
        const uint32_t* qh32 = (const uint32_t*)&g_Qh[0][0];
        const uint32_t* ql32 = (const uint32_t*)&g_Ql[0][0];
        #pragma unroll
        for (int T = 0; T < 2; T++) {
            int r0 = (nw + T * 16 + g) * 32, r1 = r0 + 8 * 32;
            #pragma unroll
            for (int ks = 0; ks < 4; ks++) {
                int o = ks * 8 + tg;
                qah[T][ks][0] = qh32[r0 + o];     qah[T][ks][1] = qh32[r1 + o];
                qah[T][ks][2] = qh32[r0 + o + 4]; qah[T][ks][3] = qh32[r1 + o + 4];
                qal[T][ks][0] = ql32[r0 + o];     qal[T][ks][1] = ql32[r1 + o];
                qal[T][ks][2] = ql32[r0 + o + 4]; qal[T][ks][3] = ql32[r1 + o + 4];
            }
        }
    }

    const char* kp = (const char*)&g_Kp[h][0][0];
    const float* beta_s = (const float*)(smem + SM_BETA);
    float* w_s = (float*)(smem + SM_W);

    float S[4] = {0.f, 0.f, 0.f, 0.f};
    float inv[4] = {0.f, 0.f, 0.f, 0.f};

    for (int pass = 0; pass < 2; pass++) {
        __syncthreads();                 // prior pass fully done with bufs
        load_chunk(smem, kp, 0, t); CPCOMMIT();
        load_chunk(smem, kp, 1, t); CPCOMMIT();

        for (int c = 0; c < 16; c++) {
            if (c < 15) { CPWAIT(1); } else { CPWAIT(0); }
            __syncthreads();

            const char* bufb = smem + SM_BUF + (c & 1) * BUFSZ;
            const char* lanebase = bufb + g * 256 + tg * 16;

            #pragma unroll
            for (int mp = 0; mp < 8; mp++) {
                float d0[2][4] = {}, d1[2][4] = {};   // fused accumulators
                const char* p0 = lanebase + mp * (16 * 256);
                #pragma unroll
                for (int ks = 0; ks < 4; ks++) {
                    uint4 v0 = *(const uint4*)(p0 + ks * 64);            // rows g
                    uint4 v1 = *(const uint4*)(p0 + 8 * 256 + ks * 64);  // rows 8+g
                    #pragma unroll
                    for (int T = 0; T < 2; T++) {
                        mma16816(d0[T], qah[T][ks], v0.x, v0.y);
                        mma16816(d1[T], qah[T][ks], v1.x, v1.y);
                        mma16816(d0[T], qal[T][ks], v0.x, v0.y);
                        mma16816(d1[T], qal[T][ks], v1.x, v1.y);
                        mma16816(d0[T], qah[T][ks], v0.z, v0.w);
                        mma16816(d1[T], qah[T][ks], v1.z, v1.w);
                    }
                }
                int mb0 = c * 128 + mp * 16;
                float2 be0 = *(const float2*)(beta_s + mb0 + 2 * tg);
                float2 be1 = *(const float2*)(beta_s + mb0 + 8 + 2 * tg);
                float v00 = 0.f, v01 = 0.f, v10 = 0.f, v11 = 0.f;
                #pragma unroll
                for (int T = 0; T < 2; T++) {
                    float e0 = ex2(d0[T][0] + be0.x);
                    float e1 = ex2(d0[T][1] + be0.y);
                    float e2 = ex2(d0[T][2] + be0.x);
                    float e3 = ex2(d0[T][3] + be0.y);
                    float f0 = ex2(d1[T][0] + be1.x);
                    float f1 = ex2(d1[T][1] + be1.y);
                    float f2 = ex2(d1[T][2] + be1.x);
                    float f3 = ex2(d1[T][3] + be1.y);
                    if (pass == 0) {
                        S[2 * T]     += (e0 + e1) + (f0 + f1);
                        S[2 * T + 1] += (e2 + e3) + (f2 + f3);
                    } else {
                        v00 += e0 * inv[2 * T] + e2 * inv[2 * T + 1];
                        v01 += e1 * inv[2 * T] + e3 * inv[2 * T + 1];
                        v10 += f0 * inv[2 * T] + f2 * inv[2 * T + 1];
                        v11 += f1 * inv[2 * T] + f3 * inv[2 * T + 1];
                    }
                }
                if (pass == 1) {
                    #pragma unroll
                    for (int off = 4; off < 32; off <<= 1) {
                        v00 += __shfl_xor_sync(0xffffffffu, v00, off);
                        v01 += __shfl_xor_sync(0xffffffffu, v01, off);
                        v10 += __shfl_xor_sync(0xffffffffu, v10, off);
                        v11 += __shfl_xor_sync(0xffffffffu, v11, off);
                    }
                    if (l < 4) {
                        atomicAdd(&w_s[mb0 + 2 * tg], v00);
                        atomicAdd(&w_s[mb0 + 2 * tg + 1], v01);
                        atomicAdd(&w_s[mb0 + 8 + 2 * tg], v10);
                        atomicAdd(&w_s[mb0 + 8 + 2 * tg + 1], v11);
                    }
                }
            }
            if (c + 2 < 16) {
                __syncthreads();
                load_chunk(smem, kp, c + 2, t); CPCOMMIT();
            }
        }
        if (pass == 0) {
            #pragma unroll
            for (int i = 0; i < 4; i++) {
                S[i] += __shfl_xor_sync(0xffffffffu, S[i], 1);
                S[i] += __shfl_xor_sync(0xffffffffu, S[i], 2);
                inv[i] = 1.f / S[i];
            }
        }
    }

    __syncthreads();
    #pragma unroll
    for (int i = 0; i < 16; i++) {
        int m = t + 128 * i;
        atomicAdd(&g_w[h][m], w_s[m]);
    }
}

// ---------------- K4a: u[h] += w[h] strip @ values strip ----------------
__global__ void k4a(const float* __restrict__ values) {
    __shared__ float w_s[512];
    __shared__ float part[4][64];
    int h = blockIdx.x, strip = blockIdx.y, t = threadIdx.x;
    int mbase = strip * 512;
    w_s[t]       = g_w[h][mbase + t];
    w_s[t + 256] = g_w[h][mbase + 256 + t];
    __syncthreads();
    int v = t & 63, s = t >> 6;
    float acc = 0.f;
    for (int m = s * 128; m < s * 128 + 128; m++)
        acc += w_s[m] * values[(mbase + m) * DKV + v];
    part[s][v] = acc;
    __syncthreads();
    if (t < 64)
        atomicAdd(&g_u[h][t], part[0][t] + part[1][t] + part[2][t] + part[3][t]);
}

// ---------------- K4b: pooled[d] += u strip . Wv strip (+ bias on strip 0) ----------------
__global__ void k4b(const float* __restrict__ Wv, const float* __restrict__ bv) {
    __shared__ float u_s[256];
    int t = threadIdx.x, d = blockIdx.x * 256 + t, strip = blockIdx.y;
    u_s[t] = ((const float*)g_u)[strip * 256 + t];
    __syncthreads();
    float acc = 0.f;
    #pragma unroll 4
    for (int hv = 0; hv < 256; hv++) acc += u_s[hv] * Wv[(strip * 256 + hv) * DMOD + d];
    if (strip == 0) {
        float bsum = 0.f;
        #pragma unroll
        for (int h2 = 0; h2 < NHEAD; h2++) bsum += bv[h2 * DMOD + d];
        acc += 2048.f * bsum;
    }
    atomicAdd(&g_pooled[d], acc);
}

// ---------------- K4c: out[d] = pooled . Wo[d,:] + bo[d] ----------------
__global__ void k4c(const float* __restrict__ Wo, const float* __restrict__ bo,
                    float* __restrict__ out) {
    __shared__ __align__(16) float p_s[1024];
    int t = threadIdx.x;
    #pragma unroll
    for (int j = 0; j < 4; j++) p_s[t + 256 * j] = g_pooled[t + 256 * j];
    __syncthreads();
    int w = t >> 5, l = t & 31, d = blockIdx.x * 8 + w;
    float acc = 0.f;
    #pragma unroll
    for (int i = 0; i < 8; i++) {
        int e = i * 128 + l * 4;
        float4 wo = *(const float4*)&Wo[d * 1024 + e];
        float4 p  = *(const float4*)&p_s[e];
        acc += wo.x * p.x + wo.y * p.y + wo.z * p.z + wo.w * p.w;
    }
    #pragma unroll
    for (int off = 16; off; off >>= 1) acc += __shfl_xor_sync(0xffffffffu, acc, off);
    if (l == 0) out[d] = acc + bo[d];
}

// ---------------- launch ----------------
extern "C" void kernel_launch(void* const* d_in, const int* in_sizes, int n_in,
                              void* d_out, int out_size) {
    const float* queries = (const float*)d_in[0];
    const float* keys    = (const float*)d_in[1];
    const float* values  = (const float*)d_in[2];
    const float* Wq      = (const float*)d_in[3];
    const float* bq      = (const float*)d_in[4];
    const float* Wk      = (const float*)d_in[5];
    (void)d_in[6];  // bk: row-constant in softmax -> drops
    const float* Wv      = (const float*)d_in[7];
    const float* bv      = (const float*)d_in[8];
    const float* Wo      = (const float*)d_in[9];
    const float* bo      = (const float*)d_in[10];
    float* out = (float*)d_out;

    cudaFuncSetAttribute(k3, cudaFuncAttributeMaxDynamicSharedMemorySize, SM_TOT);

    kq <<<512, 256>>>(queries);
    k1 <<<dim3(16, 16), 256>>>(Wq, Wk, bq);
    k2 <<<dim3(32, 16), 256>>>(keys);
    k3 <<<dim3(16, 16), 128, SM_TOT>>>();
    k4a<<<dim3(16, 4), 256>>>(values);
    k4b<<<dim3(4, 4), 256>>>(Wv, bv);
    k4c<<<128, 256>>>(Wo, bo, out);
}